// round 13
// baseline (speedup 1.0000x reference)
#include <cuda_runtime.h>
#include <cuda_fp16.h>
#include <cstdint>

#define DINLINE __device__ __forceinline__

// ---------------- device scratch (no dynamic alloc allowed) ----------------
static __device__ __align__(16) __half g_xh[8192 * 1024];
static __device__ __align__(16) __half g_fh[3072 * 1024];

// ---------------- portable PTX helpers (sm_80-class ISA only) ----------------
DINLINE uint32_t smem_u32(const void* p) {
    uint32_t a;
    asm("{ .reg .u64 t; cvta.to.shared.u64 t, %1; cvt.u32.u64 %0, t; }" : "=r"(a) : "l"(p));
    return a;
}
DINLINE void cp_async16(uint32_t dst, const void* src) {
    asm volatile("cp.async.cg.shared.global [%0], [%1], 16;" :: "r"(dst), "l"(src) : "memory");
}
DINLINE void cp_commit() { asm volatile("cp.async.commit_group;" ::: "memory"); }
DINLINE void cp_wait0() { asm volatile("cp.async.wait_group 0;" ::: "memory"); }

DINLINE void ldsm4(uint32_t* r, uint32_t addr) {
    asm volatile("ldmatrix.sync.aligned.m8n8.x4.shared.b16 {%0,%1,%2,%3}, [%4];"
                 : "=r"(r[0]), "=r"(r[1]), "=r"(r[2]), "=r"(r[3]) : "r"(addr));
}
DINLINE void mma_f16(float* c, const uint32_t* a, const uint32_t* b) {
    asm volatile(
        "mma.sync.aligned.m16n8k16.row.col.f32.f16.f16.f32 "
        "{%0,%1,%2,%3}, {%4,%5,%6,%7}, {%8,%9}, {%0,%1,%2,%3};"
        : "+f"(c[0]), "+f"(c[1]), "+f"(c[2]), "+f"(c[3])
        : "r"(a[0]), "r"(a[1]), "r"(a[2]), "r"(a[3]), "r"(b[0]), "r"(b[1]));
}

DINLINE uint32_t pack_h2(__half a, __half b) {
    __half2 t = __halves2half2(a, b);
    return *reinterpret_cast<uint32_t*>(&t);
}

// ==================== kernel 1: merged prologue ====================
// blocks [0, 8192):    convert x -> fp16 into g_xh
// blocks [8192, 8576): rotate W -> filt (fp16) into g_fh
__global__ void __launch_bounds__(256, 4) prep_kernel(
    const float4* __restrict__ x4, const float* __restrict__ W,
    const float* __restrict__ qR, const float* __restrict__ kR,
    const float* __restrict__ vR) {
    if (blockIdx.x < 8192) {
        int i = blockIdx.x * 256 + threadIdx.x;   // 2,097,152 float4s total
        float4 v = x4[i];
        reinterpret_cast<uint2*>(g_xh)[i] =
            make_uint2(pack_h2(__float2half(v.x), __float2half(v.y)),
                       pack_h2(__float2half(v.z), __float2half(v.w)));
        return;
    }

    // rotate: filt[o, r*128+j] = sum_i W[o, r*128+i] * R_sel[r, i, j]
    __shared__ float sW[64][128];
    int b = blockIdx.x - 8192;         // 384 blocks: 48 o-tiles x 8 r-blocks
    int o0 = (b >> 3) * 64;
    int r  = b & 7;
    int tid = threadIdx.x;
    int tx = tid & 127;                // j: 0..127
    int ty = tid >> 7;                 // 0..1

    for (int idx = tid; idx < 64 * 128; idx += 256) {
        int row = idx >> 7, i = idx & 127;
        sW[row][i] = W[(size_t)(o0 + row) * 1024 + r * 128 + i];
    }
    __syncthreads();

    const float* R = ((o0 < 1024) ? qR : (o0 < 2048) ? kR : vR) + (size_t)r * 16384;

    float acc[32];
#pragma unroll
    for (int oo = 0; oo < 32; oo++) acc[oo] = 0.0f;

#pragma unroll 4
    for (int i4 = 0; i4 < 32; i4++) {
        float r0 = R[(i4 * 4 + 0) * 128 + tx];
        float r1 = R[(i4 * 4 + 1) * 128 + tx];
        float r2 = R[(i4 * 4 + 2) * 128 + tx];
        float r3 = R[(i4 * 4 + 3) * 128 + tx];
#pragma unroll
        for (int oo = 0; oo < 32; oo++) {
            float4 w = *reinterpret_cast<const float4*>(&sW[ty * 32 + oo][i4 * 4]);
            acc[oo] = fmaf(w.x, r0, fmaf(w.y, r1, fmaf(w.z, r2, fmaf(w.w, r3, acc[oo]))));
        }
    }

#pragma unroll
    for (int oo = 0; oo < 32; oo++) {
        int o = o0 + ty * 32 + oo;
        g_fh[(size_t)o * 1024 + r * 128 + tx] = __float2half(acc[oo]);
    }
}

// ==================== kernel 2: HMMA GEMM ====================
// out[8192,3072] = Xh*Fh^T + bias
//
// BM=128, BN=128, BK=64, 2-stage cp.async pipeline, 128 threads (4 warps),
// 3 CTAs/SM (12 warps/SM). Warp layout 2(M) x 2(N); warp tile 64x64.
// Single-buffered fragments (regs ~168 <= 170 cap) — ldsm latency is covered
// by the other CTAs' dense mma chains. Stage s+1's cp.async is issued right
// after the barrier and completes under stage s's ~3072-cyc compute window.
// XOR swizzle on 128B rows: 16B-chunk c' = c ^ (row & 7).
static constexpr int BM = 128, BN = 128, BK = 64;
static constexpr int NCHUNKS = 1024 / BK;       // 16
static constexpr int STAGE_BYTES = 32768;
static constexpr int SMEM_SIZE = 2 * STAGE_BYTES;   // 64KB -> 3 CTAs/SM (192KB)

DINLINE uint32_t swz(int row, int chunk) {            // byte offset within one 16KB array
    return (uint32_t)(row * 128 + (chunk ^ (row & 7)) * 16);
}

DINLINE void load_stage(uint32_t sbase, int m0, int n0, int k0, int tid) {
    // 2 arrays x 128 rows x 8 chunks = 2048 cp.async / 128 threads = 16 each
#pragma unroll
    for (int t = 0; t < 16; t++) {
        int idx = tid + t * 128;
        int arr = idx >> 10;         // 0:A 1:B
        int rem = idx & 1023;
        int row = rem >> 3, chunk = rem & 7;
        const __half* src = (arr == 0)
            ? g_xh + (size_t)(m0 + row) * 1024 + k0 + chunk * 8
            : g_fh + (size_t)(n0 + row) * 1024 + k0 + chunk * 8;
        cp_async16(sbase + arr * 16384 + swz(row, chunk), src);
    }
}

__global__ void __launch_bounds__(128, 3) gemm_kernel(
    const float* __restrict__ bias, float* __restrict__ out) {
    extern __shared__ __align__(128) char smem[];
    uint32_t sm0 = smem_u32(smem);

    int tid = threadIdx.x;
    int wid = tid >> 5, lane = tid & 31;
    int warp_m = wid & 1;                 // 2 warps in M
    int warp_n = wid >> 1;                // 2 warps in N
    int wm = warp_m * 64;                 // warp tile 64 x 64
    int wn = warp_n * 64;
    int m0 = blockIdx.x * BM;
    int n0 = blockIdx.y * BN;

    // per-lane ldmatrix row/half decomposition (validated mapping)
    int a_r    = lane & 15;               // A rows; lanes 16-31 -> k8 half 1
    int a_half = lane >> 4;
    int b_r    = ((lane >> 4) << 3) | (lane & 7);  // B: n-row
    int b_half = (lane >> 3) & 1;                  // k half

    float acc[4][8][4];
#pragma unroll
    for (int i = 0; i < 4; i++)
#pragma unroll
        for (int j = 0; j < 8; j++)
#pragma unroll
            for (int q = 0; q < 4; q++) acc[i][j][q] = 0.0f;

    // prologue: stage 0
    load_stage(sm0, m0, n0, 0, tid); cp_commit();

    uint32_t af[4][4];   // [mt][frag] single-buffered
    uint32_t bf[4][4];   // [nt][frag]

    for (int s = 0; s < NCHUNKS; s++) {
        cp_wait0();
        __syncthreads();

        // issue next stage's load immediately; it completes under this
        // stage's compute (per-SM feed ~2300 cyc < ~3072 cyc compute)
        if (s + 1 < NCHUNKS) {
            load_stage(sm0 + ((s + 1) & 1) * STAGE_BYTES, m0, n0, (s + 1) * BK, tid);
            cp_commit();
        }

        uint32_t sb = sm0 + (s & 1) * STAGE_BYTES;
        uint32_t sA = sb, sB = sb + 16384;

#pragma unroll
        for (int kk = 0; kk < 4; kk++) {       // four k16 steps per 64-chunk
            int kb = kk * 2;
#pragma unroll
            for (int mt = 0; mt < 4; mt++)
                ldsm4(af[mt], sA + swz(wm + mt * 16 + a_r, kb + a_half));
#pragma unroll
            for (int nt = 0; nt < 4; nt++)
                ldsm4(bf[nt], sB + swz(wn + nt * 16 + b_r, kb + b_half));
#pragma unroll
            for (int mt = 0; mt < 4; mt++)
#pragma unroll
                for (int n8 = 0; n8 < 8; n8++)
                    mma_f16(acc[mt][n8], af[mt], &bf[n8 >> 1][(n8 & 1) * 2]);
        }

        // last stage read complete before next loop's load overwrites buffer
        __syncthreads();
    }

    // epilogue: C frag lane mapping: rows l/4, l/4+8; cols (l%4)*2, +1
    int cr = lane >> 2, cc = (lane & 3) * 2;
#pragma unroll
    for (int mt = 0; mt < 4; mt++) {
#pragma unroll
        for (int n8 = 0; n8 < 8; n8++) {
            int col = n0 + wn + n8 * 8 + cc;
            float b0 = __ldg(bias + col), b1 = __ldg(bias + col + 1);
            int row0 = m0 + wm + mt * 16 + cr;
            float2 v0 = make_float2(acc[mt][n8][0] + b0, acc[mt][n8][1] + b1);
            float2 v1 = make_float2(acc[mt][n8][2] + b0, acc[mt][n8][3] + b1);
            *reinterpret_cast<float2*>(out + (size_t)row0 * 3072 + col) = v0;
            *reinterpret_cast<float2*>(out + (size_t)(row0 + 8) * 3072 + col) = v1;
        }
    }
}

// ==================== host ====================
extern "C" void kernel_launch(void* const* d_in, const int* in_sizes, int n_in,
                              void* d_out, int out_size) {
    const float* attn = (const float*)d_in[0];   // [3072, 1024]
    const float* bias = (const float*)d_in[1];   // [3072]
    const float* x    = (const float*)d_in[2];   // [4, 2048, 1024]
    const float* qR   = (const float*)d_in[3];   // [8, 128, 128]
    const float* kR   = (const float*)d_in[4];
    const float* vR   = (const float*)d_in[5];
    float* out = (float*)d_out;                  // [8192, 3072]

    prep_kernel<<<8192 + 384, 256>>>(reinterpret_cast<const float4*>(x),
                                     attn, qR, kR, vR);

    cudaFuncSetAttribute(gemm_kernel, cudaFuncAttributeMaxDynamicSharedMemorySize, SMEM_SIZE);
    gemm_kernel<<<dim3(64, 24), 128, SMEM_SIZE>>>(bias, out);
}

// round 14
// speedup vs baseline: 1.3219x; 1.3219x over previous
#include <cuda_runtime.h>
#include <cuda_fp16.h>
#include <cstdint>

#define DINLINE __device__ __forceinline__

// ---------------- device scratch (no dynamic alloc allowed) ----------------
static __device__ __align__(16) __half g_xh[8192 * 1024];
static __device__ __align__(16) __half g_fh[3072 * 1024];

// ---------------- portable PTX helpers (sm_80-class ISA only) ----------------
DINLINE uint32_t smem_u32(const void* p) {
    uint32_t a;
    asm("{ .reg .u64 t; cvta.to.shared.u64 t, %1; cvt.u32.u64 %0, t; }" : "=r"(a) : "l"(p));
    return a;
}
DINLINE void cp_async16(uint32_t dst, const void* src) {
    asm volatile("cp.async.cg.shared.global [%0], [%1], 16;" :: "r"(dst), "l"(src) : "memory");
}
DINLINE void cp_commit() { asm volatile("cp.async.commit_group;" ::: "memory"); }
DINLINE void cp_wait0() { asm volatile("cp.async.wait_group 0;" ::: "memory"); }
DINLINE void cp_wait1() { asm volatile("cp.async.wait_group 1;" ::: "memory"); }

DINLINE void ldsm4(uint32_t* r, uint32_t addr) {
    asm volatile("ldmatrix.sync.aligned.m8n8.x4.shared.b16 {%0,%1,%2,%3}, [%4];"
                 : "=r"(r[0]), "=r"(r[1]), "=r"(r[2]), "=r"(r[3]) : "r"(addr));
}
DINLINE void mma_f16(float* c, const uint32_t* a, const uint32_t* b) {
    asm volatile(
        "mma.sync.aligned.m16n8k16.row.col.f32.f16.f16.f32 "
        "{%0,%1,%2,%3}, {%4,%5,%6,%7}, {%8,%9}, {%0,%1,%2,%3};"
        : "+f"(c[0]), "+f"(c[1]), "+f"(c[2]), "+f"(c[3])
        : "r"(a[0]), "r"(a[1]), "r"(a[2]), "r"(a[3]), "r"(b[0]), "r"(b[1]));
}

DINLINE uint32_t pack_h2(__half a, __half b) {
    __half2 t = __halves2half2(a, b);
    return *reinterpret_cast<uint32_t*>(&t);
}

// XOR swizzle on 128B rows: 16B-chunk c' = c ^ (row & 7)
DINLINE uint32_t swz(int row, int chunk) {
    return (uint32_t)(row * 128 + (chunk ^ (row & 7)) * 16);
}

// ==================== kernel 1: merged prologue ====================
// blocks [0, 1024):     convert x -> fp16 (8 float4/thread, MLP=8)
// blocks [1024, 1216):  rotate W -> filt via HMMA (fp16 inputs, fp32 acc)
//   rotate block b: o-tile (b>>3)*128 rows, r-block b&7.
//   filt[o, r*128+j] = sum_i W[o, r*128+i] * R_sel[r, i, j]
//   A = W tile [128 x 128] fp16 (row-major k), B[n=j][k=i] = R[i][j] (R^T).
__global__ void __launch_bounds__(256, 2) prep_kernel(
    const float4* __restrict__ x4, const float* __restrict__ W,
    const float* __restrict__ qR, const float* __restrict__ kR,
    const float* __restrict__ vR) {
    if (blockIdx.x < 1024) {
        int base = blockIdx.x * 2048 + threadIdx.x;
#pragma unroll
        for (int t = 0; t < 8; t++) {
            int i = base + t * 256;
            float4 v = x4[i];
            reinterpret_cast<uint2*>(g_xh)[i] =
                make_uint2(pack_h2(__float2half(v.x), __float2half(v.y)),
                           pack_h2(__float2half(v.z), __float2half(v.w)));
        }
        return;
    }

    // ---------------- rotate via HMMA ----------------
    extern __shared__ __align__(128) char smem[];
    uint32_t sm0 = smem_u32(smem);
    // sA0: k[0,64), sA1: k[64,128), sB0, sB1 likewise; each 128 rows x 128B
    uint32_t sA[2] = {sm0, sm0 + 16384};
    uint32_t sB[2] = {sm0 + 32768, sm0 + 49152};

    int b = blockIdx.x - 1024;          // 0..191
    int o0 = (b >> 3) * 128;            // 24 o-tiles
    int r  = b & 7;
    int tid = threadIdx.x;
    int wid = tid >> 5, lane = tid & 31;

    // load W tile [128 x 128] fp32 -> fp16, swizzled (half2 units, coalesced)
    for (int u = tid; u < 128 * 64; u += 256) {
        int row = u >> 6;
        int col = (u & 63) * 2;
        const float2 w = *reinterpret_cast<const float2*>(
            W + (size_t)(o0 + row) * 1024 + r * 128 + col);
        int arr = col >> 6, c0 = col & 63;
        uint32_t dst = sA[arr] + swz(row, c0 >> 3) + (c0 & 7) * 2;
        *reinterpret_cast<__half2*>((char*)nullptr + 0); // (no-op placeholder removed below)
        asm volatile("st.shared.b32 [%0], %1;" :: "r"(dst),
                     "r"(pack_h2(__float2half(w.x), __float2half(w.y))) : "memory");
    }

    // load R^T: B[j][i] = R[i][j]; lanes vary i (conflict-light smem stores)
    const float* R = ((o0 < 1024) ? qR : (o0 < 2048) ? kR : vR) + (size_t)r * 16384;
    for (int u = tid; u < 128 * 128; u += 256) {
        int i = u & 127;                // k index (lane-fastest)
        int j = u >> 7;                 // n index
        __half h = __float2half(R[i * 128 + j]);
        int arr = i >> 6, c0 = i & 63;
        uint32_t dst = sB[arr] + swz(j, c0 >> 3) + (c0 & 7) * 2;
        uint16_t hb = *reinterpret_cast<uint16_t*>(&h);
        asm volatile("st.shared.b16 [%0], %1;" :: "r"(dst), "h"(hb) : "memory");
    }
    __syncthreads();

    // 8 warps: 2(M) x 4(N); warp tile 64 x 32
    int wm = (wid & 1) * 64;
    int wn = (wid >> 1) * 32;
    int a_r    = lane & 15;
    int a_half = lane >> 4;
    int b_r    = ((lane >> 4) << 3) | (lane & 7);
    int b_half = (lane >> 3) & 1;

    float acc[4][4][4];
#pragma unroll
    for (int i = 0; i < 4; i++)
#pragma unroll
        for (int j = 0; j < 4; j++)
#pragma unroll
            for (int q = 0; q < 4; q++) acc[i][j][q] = 0.0f;

#pragma unroll
    for (int arr = 0; arr < 2; arr++) {
#pragma unroll
        for (int kk = 0; kk < 4; kk++) {
            int kb = kk * 2;
            uint32_t af[4][4], bfr[2][4];
#pragma unroll
            for (int mt = 0; mt < 4; mt++)
                ldsm4(af[mt], sA[arr] + swz(wm + mt * 16 + a_r, kb + a_half));
#pragma unroll
            for (int nt = 0; nt < 2; nt++)
                ldsm4(bfr[nt], sB[arr] + swz(wn + nt * 16 + b_r, kb + b_half));
#pragma unroll
            for (int mt = 0; mt < 4; mt++)
#pragma unroll
                for (int n8 = 0; n8 < 4; n8++)
                    mma_f16(acc[mt][n8], af[mt], &bfr[n8 >> 1][(n8 & 1) * 2]);
        }
    }

    // store filt tile as fp16
    int cr = lane >> 2, cc = (lane & 3) * 2;
#pragma unroll
    for (int mt = 0; mt < 4; mt++) {
#pragma unroll
        for (int n8 = 0; n8 < 4; n8++) {
            int col = wn + n8 * 8 + cc;                 // j within r-block
            int row0 = o0 + wm + mt * 16 + cr;
            __half2 v0 = __floats2half2_rn(acc[mt][n8][0], acc[mt][n8][1]);
            __half2 v1 = __floats2half2_rn(acc[mt][n8][2], acc[mt][n8][3]);
            *reinterpret_cast<__half2*>(g_fh + (size_t)row0 * 1024 + r * 128 + col) = v0;
            *reinterpret_cast<__half2*>(g_fh + (size_t)(row0 + 8) * 1024 + r * 128 + col) = v1;
        }
    }
}

// ==================== kernel 2: HMMA GEMM (R12 config, best measured) ====================
// out[8192,3072] = Xh*Fh^T + bias
// BM=128, BN=128, BK=64, 3-stage cp.async pipeline, 128 threads (4 warps),
// 2 CTAs/SM. Warp layout 2(M) x 2(N); warp tile 64x64. Double-buffered frags.
static constexpr int BM = 128, BN = 128, BK = 64;
static constexpr int NCHUNKS = 1024 / BK;       // 16
static constexpr int STAGE_BYTES = 32768;
static constexpr int SMEM_SIZE = 3 * STAGE_BYTES;   // 96KB -> 2 CTAs/SM

DINLINE void load_stage(uint32_t sbase, int m0, int n0, int k0, int tid) {
#pragma unroll
    for (int t = 0; t < 16; t++) {
        int idx = tid + t * 128;
        int arr = idx >> 10;         // 0:A 1:B
        int rem = idx & 1023;
        int row = rem >> 3, chunk = rem & 7;
        const __half* src = (arr == 0)
            ? g_xh + (size_t)(m0 + row) * 1024 + k0 + chunk * 8
            : g_fh + (size_t)(n0 + row) * 1024 + k0 + chunk * 8;
        cp_async16(sbase + arr * 16384 + swz(row, chunk), src);
    }
}

__global__ void __launch_bounds__(128, 2) gemm_kernel(
    const float* __restrict__ bias, float* __restrict__ out) {
    extern __shared__ __align__(128) char smem[];
    uint32_t sm0 = smem_u32(smem);

    int tid = threadIdx.x;
    int wid = tid >> 5, lane = tid & 31;
    int warp_m = wid & 1;
    int warp_n = wid >> 1;
    int wm = warp_m * 64;
    int wn = warp_n * 64;
    int m0 = blockIdx.x * BM;
    int n0 = blockIdx.y * BN;

    int a_r    = lane & 15;
    int a_half = lane >> 4;
    int b_r    = ((lane >> 4) << 3) | (lane & 7);
    int b_half = (lane >> 3) & 1;

    float acc[4][8][4];
#pragma unroll
    for (int i = 0; i < 4; i++)
#pragma unroll
        for (int j = 0; j < 8; j++)
#pragma unroll
            for (int q = 0; q < 4; q++) acc[i][j][q] = 0.0f;

    load_stage(sm0, m0, n0, 0, tid); cp_commit();
    load_stage(sm0 + STAGE_BYTES, m0, n0, BK, tid); cp_commit();

    uint32_t af[2][4][4];
    uint32_t bf[2][4][4];

    for (int s = 0; s < NCHUNKS; s++) {
        if (s < NCHUNKS - 1) cp_wait1(); else cp_wait0();
        __syncthreads();

        uint32_t sb = sm0 + (s % 3) * STAGE_BYTES;
        uint32_t sA = sb, sB = sb + 16384;

#pragma unroll
        for (int mt = 0; mt < 4; mt++)
            ldsm4(af[0][mt], sA + swz(wm + mt * 16 + a_r, a_half));
#pragma unroll
        for (int nt = 0; nt < 4; nt++)
            ldsm4(bf[0][nt], sB + swz(wn + nt * 16 + b_r, b_half));

        if (s + 2 < NCHUNKS) {
            load_stage(sm0 + ((s + 2) % 3) * STAGE_BYTES, m0, n0, (s + 2) * BK, tid);
            cp_commit();
        }

#pragma unroll
        for (int kk = 0; kk < 4; kk++) {
            int cur = kk & 1, nxt = cur ^ 1;
            if (kk < 3) {
                int kb = (kk + 1) * 2;
#pragma unroll
                for (int mt = 0; mt < 4; mt++)
                    ldsm4(af[nxt][mt], sA + swz(wm + mt * 16 + a_r, kb + a_half));
#pragma unroll
                for (int nt = 0; nt < 4; nt++)
                    ldsm4(bf[nxt][nt], sB + swz(wn + nt * 16 + b_r, kb + b_half));
            }
#pragma unroll
            for (int mt = 0; mt < 4; mt++)
#pragma unroll
                for (int n8 = 0; n8 < 8; n8++)
                    mma_f16(acc[mt][n8], af[cur][mt], &bf[cur][n8 >> 1][(n8 & 1) * 2]);
        }
    }

    int cr = lane >> 2, cc = (lane & 3) * 2;
#pragma unroll
    for (int mt = 0; mt < 4; mt++) {
#pragma unroll
        for (int n8 = 0; n8 < 8; n8++) {
            int col = n0 + wn + n8 * 8 + cc;
            float b0 = __ldg(bias + col), b1 = __ldg(bias + col + 1);
            int row0 = m0 + wm + mt * 16 + cr;
            float2 v0 = make_float2(acc[mt][n8][0] + b0, acc[mt][n8][1] + b1);
            float2 v1 = make_float2(acc[mt][n8][2] + b0, acc[mt][n8][3] + b1);
            *reinterpret_cast<float2*>(out + (size_t)row0 * 3072 + col) = v0;
            *reinterpret_cast<float2*>(out + (size_t)(row0 + 8) * 3072 + col) = v1;
        }
    }
}

// ==================== host ====================
extern "C" void kernel_launch(void* const* d_in, const int* in_sizes, int n_in,
                              void* d_out, int out_size) {
    const float* attn = (const float*)d_in[0];   // [3072, 1024]
    const float* bias = (const float*)d_in[1];   // [3072]
    const float* x    = (const float*)d_in[2];   // [4, 2048, 1024]
    const float* qR   = (const float*)d_in[3];   // [8, 128, 128]
    const float* kR   = (const float*)d_in[4];
    const float* vR   = (const float*)d_in[5];
    float* out = (float*)d_out;                  // [8192, 3072]

    cudaFuncSetAttribute(prep_kernel, cudaFuncAttributeMaxDynamicSharedMemorySize, 65536);
    prep_kernel<<<1024 + 192, 256, 65536>>>(reinterpret_cast<const float4*>(x),
                                            attn, qR, kR, vR);

    cudaFuncSetAttribute(gemm_kernel, cudaFuncAttributeMaxDynamicSharedMemorySize, SMEM_SIZE);
    gemm_kernel<<<dim3(64, 24), 128, SMEM_SIZE>>>(bias, out);
}